// round 12
// baseline (speedup 1.0000x reference)
#include <cuda_runtime.h>
#include <cuda_fp16.h>
#include <cstdint>

// Problem dims
#define LSEQ 32768
#define HDIM 256
#define PDIM 128
#define TCH  64                   // scan chunk length
#define NCHUNK (LSEQ / TCH)       // 512

// ---------------------------------------------------------------------------
__device__ __forceinline__ uint32_t smem_u32(const void* p) {
    uint32_t a;
    asm("{ .reg .u64 t; cvta.to.shared.u64 t, %1; cvt.u32.u64 %0, t; }" : "=r"(a) : "l"(p));
    return a;
}
__device__ __forceinline__ void ldsm_x4(uint32_t (&r)[4], uint32_t addr) {
    asm volatile("ldmatrix.sync.aligned.m8n8.x4.shared.b16 {%0,%1,%2,%3}, [%4];"
        : "=r"(r[0]), "=r"(r[1]), "=r"(r[2]), "=r"(r[3]) : "r"(addr));
}
__device__ __forceinline__ void mma_f16(float (&d)[4], const uint32_t (&a)[4],
                                        uint32_t b0, uint32_t b1) {
    asm volatile("mma.sync.aligned.m16n8k16.row.col.f32.f16.f16.f32 "
        "{%0,%1,%2,%3}, {%4,%5,%6,%7}, {%8,%9}, {%0,%1,%2,%3};"
        : "+f"(d[0]), "+f"(d[1]), "+f"(d[2]), "+f"(d[3])
        : "r"(a[0]), "r"(a[1]), "r"(a[2]), "r"(a[3]), "r"(b0), "r"(b1));
}
__device__ __forceinline__ void cp_async16(uint32_t dst, const void* src) {
    asm volatile("cp.async.cg.shared.global [%0], [%1], 16;" :: "r"(dst), "l"(src));
}
#define CP_COMMIT() asm volatile("cp.async.commit_group;")
#define CP_WAIT0()  asm volatile("cp.async.wait_group 0;")

// -------- device scratch (static) ------------------------------------------
__device__ __align__(128) __half g_W1h[256 * 256];  // GEMM1 B (fp16): [n=2p+ri][k=h]
__device__ __align__(128) __half g_W2h[256 * 256];  // GEMM2 B (fp16): [n=h][k=2p+ri]
__device__ float2 g_lam[PDIM];
__device__ float2 g_lamT[PDIM];
__device__ float2 g_lampow[TCH * PDIM];             // lambda^(t+1)
__device__ __align__(128) __half g_Bu16[LSEQ * 256];  // 16 MB: x_local in fp16
__device__ float2 g_carry[NCHUNK * PDIM];
__device__ float2 g_pfx[NCHUNK * PDIM];

// ---------------------------------------------------------------------------
// Prep
// ---------------------------------------------------------------------------
__global__ void prep_kernel(const float* __restrict__ Lre,
                            const float* __restrict__ Lim,
                            const float* __restrict__ B,
                            const float* __restrict__ C,
                            const float* __restrict__ logstep) {
    const int p = blockIdx.x;
    const int h = threadIdx.x;

    const float step = expf(logstep[p]);
    const float lr = Lre[p], li = Lim[p];
    const float ar = lr * step, ai = li * step;

    float s, c;
    const float mag = expf(ar);
    sincosf(ai, &s, &c);
    const float lam_re = mag * c, lam_im = mag * s;

    const float dr = lam_re - 1.0f, di = lam_im;
    const float inv_den = 1.0f / (lr * lr + li * li);
    const float fr = (dr * lr + di * li) * inv_den;
    const float fi = (di * lr - dr * li) * inv_den;

    const float b0 = B[(p * HDIM + h) * 2 + 0];
    const float b1 = B[(p * HDIM + h) * 2 + 1];
    g_W1h[(2 * p + 0) * 256 + h] = __float2half_rn(fr * b0 - fi * b1);
    g_W1h[(2 * p + 1) * 256 + h] = __float2half_rn(fr * b1 + fi * b0);

    g_W2h[h * 256 + 2 * p + 0] = __float2half_rn( 2.0f * C[(h * PDIM + p) * 2 + 0]);
    g_W2h[h * 256 + 2 * p + 1] = __float2half_rn(-2.0f * C[(h * PDIM + p) * 2 + 1]);

    if (h == 0) g_lam[p] = make_float2(lam_re, lam_im);

    if (h < TCH) {
        const float t = (float)(h + 1);
        float ss, cc;
        const float m = expf(ar * t);
        sincosf(ai * t, &ss, &cc);
        float2 pw = make_float2(m * cc, m * ss);
        g_lampow[h * PDIM + p] = pw;
        if (h == TCH - 1) g_lamT[p] = pw;
    }
}

// ---------------------------------------------------------------------------
// HMMA GEMM: CTA tile 64x64, BK=64, 4 warps (2x2), warp tile 32x32,
// 128 threads, 4 CTAs/SM (4 independent barrier domains).
// MODE 0: A=u (fp32), B=W1 -> Bu; epilogue: local scan in SMEM, write fp16 x_local
// MODE 1: A=x_local (fp16 + fused prefix fix), B=W2 -> y (+ D*u)
// ---------------------------------------------------------------------------
#define NTHREADS 128
#define STAGE_SZ 16384               // A 8K | B 8K
#define OFF_A   0
#define OFF_B   8192
#define XS_STRIDE 68                 // floats per row in epilogue staging
#define SM_TOTAL  (2 * STAGE_SZ)     // 32768

template <int MODE>
__global__ __launch_bounds__(NTHREADS, 4)
void gemm_hmma_kernel(const float* __restrict__ u,
                      float* __restrict__ y,
                      const float* __restrict__ Dv) {
    extern __shared__ char smem[];
    const uint32_t smem_base = smem_u32(smem);
    const int tid = threadIdx.x;
    const int wid = tid >> 5;
    const int lane = tid & 31;
    const int warp_m = wid >> 1;       // 0..1 (32 rows each)
    const int warp_n = wid & 1;        // 0..1 (32 cols each)
    const int n0 = blockIdx.x * 64;
    const int m0 = blockIdx.y * 64;

    const __half* Bhp = (MODE == 0) ? g_W1h : g_W2h;

    float acc[8][4];
#pragma unroll
    for (int i = 0; i < 8; i++)
#pragma unroll
        for (int j = 0; j < 4; j++) acc[i][j] = 0.0f;

    // prefetched, already-fp16-packed A data
    uint2 aReg2[8];   // MODE 0
    uint4 aReg4[4];   // MODE 1

    auto loadA = [&](int c) {
        if (MODE == 0) {
#pragma unroll
            for (int j = 0; j < 8; j++) {
                const int i4 = tid + j * NTHREADS;   // 1024 float4s (64x64 fp32)
                const int row = i4 >> 4;
                const int fc = (i4 & 15) << 2;
                const float4 v = *reinterpret_cast<const float4*>(
                    u + (size_t)(m0 + row) * 256 + c * 64 + fc);
                uint2 hv;
                hv.x = ((uint32_t)__half_as_ushort(__float2half_rn(v.y)) << 16) |
                       __half_as_ushort(__float2half_rn(v.x));
                hv.y = ((uint32_t)__half_as_ushort(__float2half_rn(v.w)) << 16) |
                       __half_as_ushort(__float2half_rn(v.z));
                aReg2[j] = hv;
            }
        } else {
#pragma unroll
            for (int j = 0; j < 4; j++) {
                const int idx = tid + j * NTHREADS;  // 512 uint4s (64x64 fp16)
                const int row = idx >> 3;
                const int g8 = (idx & 7) << 3;       // half-col within chunk
                const uint4 v = *reinterpret_cast<const uint4*>(
                    g_Bu16 + (size_t)(m0 + row) * 256 + c * 64 + g8);
                const __half2* hp = reinterpret_cast<const __half2*>(&v);
                const int l = m0 + row;
                const int pp = (c * 64 + g8) >> 1;
                const float2* pwp = g_lampow + (l & 63) * 128 + pp;
                const float2* cfp = g_pfx + (l >> 6) * 128 + pp;
                uint4 o;
                uint32_t* op = reinterpret_cast<uint32_t*>(&o);
#pragma unroll
                for (int q = 0; q < 4; q++) {
                    float2 f = __half22float2(hp[q]);
                    const float2 pw = pwp[q];
                    const float2 cf = cfp[q];
                    f.x += pw.x * cf.x - pw.y * cf.y;
                    f.y += pw.x * cf.y + pw.y * cf.x;
                    op[q] = (uint32_t)__half_as_ushort(__float2half_rn(f.y)) << 16 |
                            __half_as_ushort(__float2half_rn(f.x));
                }
                aReg4[j] = o;
            }
        }
    };
    auto storeA = [&](int buf) {
        if (MODE == 0) {
#pragma unroll
            for (int j = 0; j < 8; j++) {
                const int i4 = tid + j * NTHREADS;
                const int row = i4 >> 4;
                const int fc = (i4 & 15) << 2;
                const uint32_t off = (uint32_t)(buf * STAGE_SZ + row * 128 +
                                     (((fc >> 3) ^ (row & 7)) << 4) + ((fc & 4) << 1));
                *reinterpret_cast<uint2*>(smem + OFF_A + off) = aReg2[j];
            }
        } else {
#pragma unroll
            for (int j = 0; j < 4; j++) {
                const int idx = tid + j * NTHREADS;
                const int row = idx >> 3;
                const int un = idx & 7;
                const uint32_t off = (uint32_t)(buf * STAGE_SZ + row * 128 +
                                     ((un ^ (row & 7)) << 4));
                *reinterpret_cast<uint4*>(smem + OFF_A + off) = aReg4[j];
            }
        }
    };
    auto issueB = [&](int c, int buf) {
#pragma unroll
        for (int j = 0; j < 4; j++) {
            const int i = tid + j * NTHREADS;      // 512 16B units (64x64 fp16)
            const int row = i >> 3;
            const int un = i & 7;
            const uint32_t off = (uint32_t)(buf * STAGE_SZ + row * 128 +
                                 ((un ^ (row & 7)) << 4));
            cp_async16(smem_base + OFF_B + off,
                       Bhp + (size_t)(n0 + row) * 256 + c * 64 + un * 8);
        }
        CP_COMMIT();
    };
    auto compute = [&](int buf) {
        const uint32_t ab = smem_base + OFF_A + buf * STAGE_SZ;
        const uint32_t bb = smem_base + OFF_B + buf * STAGE_SZ;
        const int arow = (lane & 7) + ((lane >> 3) & 1) * 8;
        const int akc = lane >> 4;
        uint32_t baseA[2], baseB[2];
#pragma unroll
        for (int mi = 0; mi < 2; mi++) {
            const int row = warp_m * 32 + mi * 16 + arow;
            baseA[mi] = (uint32_t)(row * 128 + ((row & 7) << 4));
        }
#pragma unroll
        for (int hg = 0; hg < 2; hg++) {
            const int row = warp_n * 32 + hg * 16 + arow;
            baseB[hg] = (uint32_t)(row * 128 + ((row & 7) << 4));
        }
#pragma unroll
        for (int kk = 0; kk < 4; kk++) {
            const uint32_t kcx = (uint32_t)((kk * 2 + akc) << 4);
            uint32_t af[2][4], bq[2][4];
#pragma unroll
            for (int mi = 0; mi < 2; mi++)
                ldsm_x4(af[mi], ab + (baseA[mi] ^ kcx));
#pragma unroll
            for (int hg = 0; hg < 2; hg++)
                ldsm_x4(bq[hg], bb + (baseB[hg] ^ kcx));
#pragma unroll
            for (int mi = 0; mi < 2; mi++)
#pragma unroll
                for (int ni = 0; ni < 4; ni++) {
                    const int hg = ni >> 1, s2 = ni & 1;
                    mma_f16(acc[mi * 4 + ni], af[mi], bq[hg][s2], bq[hg][s2 + 2]);
                }
        }
    };

    // ---- pipelined mainloop over 4 K-chunks ----
    issueB(0, 0);
    loadA(0);
    for (int c = 0; c < 4; c++) {
        const int buf = c & 1;
        storeA(buf);
        CP_WAIT0();
        __syncthreads();
        if (c < 3) {
            issueB(c + 1, buf ^ 1);
            loadA(c + 1);
        }
        compute(buf);
    }
    __syncthreads();   // before SMEM reuse

    if (MODE == 0) {
        // ---- epilogue: stage Bu tile in SMEM, local scan, write fp16 x_local ----
        float* xs = reinterpret_cast<float*>(smem);
#pragma unroll
        for (int mi = 0; mi < 2; mi++) {
            const int r0 = warp_m * 32 + mi * 16 + (lane >> 2);
#pragma unroll
            for (int ni = 0; ni < 4; ni++) {
                const int cc = warp_n * 32 + ni * 8 + (lane & 3) * 2;
                const float* a = acc[mi * 4 + ni];
                *reinterpret_cast<float2*>(xs + r0 * XS_STRIDE + cc) = make_float2(a[0], a[1]);
                *reinterpret_cast<float2*>(xs + (r0 + 8) * XS_STRIDE + cc) = make_float2(a[2], a[3]);
            }
        }
        __syncthreads();

        if (tid < 32) {
            const int pg = (n0 >> 1) + tid;          // this CTA covers 32 states
            const float2 lam = g_lam[pg];
            float2 x = make_float2(0.0f, 0.0f);
            float* base = xs + 2 * tid;
#pragma unroll 4
            for (int t = 0; t < 64; t++) {
                float2 b = *reinterpret_cast<float2*>(base + t * XS_STRIDE);
                const float nr = lam.x * x.x - lam.y * x.y + b.x;
                const float ni2 = lam.x * x.y + lam.y * x.x + b.y;
                x.x = nr; x.y = ni2;
                *reinterpret_cast<float2*>(base + t * XS_STRIDE) = x;
            }
            g_carry[(m0 >> 6) * 128 + pg] = x;       // one chunk per CTA (BM=64=TCH)
        }
        __syncthreads();

#pragma unroll
        for (int j = 0; j < 4; j++) {
            const int idx = tid + j * NTHREADS;      // 512 uint4s (64x64 fp16)
            const int row = idx >> 3;
            const int g8 = (idx & 7) << 3;
            const float* src = xs + row * XS_STRIDE + g8;
            uint4 o;
            uint32_t* op = reinterpret_cast<uint32_t*>(&o);
#pragma unroll
            for (int q = 0; q < 4; q++) {
                const float2 f = *reinterpret_cast<const float2*>(src + 2 * q);
                op[q] = (uint32_t)__half_as_ushort(__float2half_rn(f.y)) << 16 |
                        __half_as_ushort(__float2half_rn(f.x));
            }
            *reinterpret_cast<uint4*>(g_Bu16 + (size_t)(m0 + row) * 256 + n0 + g8) = o;
        }
    } else {
        // ---- epilogue: y = acc + D*u, direct ----
#pragma unroll
        for (int mi = 0; mi < 2; mi++) {
            const int r0 = m0 + warp_m * 32 + mi * 16 + (lane >> 2);
#pragma unroll
            for (int ni = 0; ni < 4; ni++) {
                const int gc = n0 + warp_n * 32 + ni * 8 + (lane & 3) * 2;
                const float d0 = __ldg(Dv + gc), d1 = __ldg(Dv + gc + 1);
                const float* a = acc[mi * 4 + ni];
                const float2 u0 = *reinterpret_cast<const float2*>(u + (size_t)r0 * 256 + gc);
                const float2 u1 = *reinterpret_cast<const float2*>(u + (size_t)(r0 + 8) * 256 + gc);
                *reinterpret_cast<float2*>(y + (size_t)r0 * 256 + gc) =
                    make_float2(a[0] + d0 * u0.x, a[1] + d1 * u0.y);
                *reinterpret_cast<float2*>(y + (size_t)(r0 + 8) * 256 + gc) =
                    make_float2(a[2] + d0 * u1.x, a[3] + d1 * u1.y);
            }
        }
    }
}

// ---------------------------------------------------------------------------
// Parallel carry scan across chunks (Kogge-Stone), exclusive prefix -> g_pfx.
// ---------------------------------------------------------------------------
__global__ __launch_bounds__(NCHUNK)
void carry_scan_par_kernel() {
    const int p = blockIdx.x;
    const int j = threadIdx.x;
    __shared__ float2 sa[2][NCHUNK];
    __shared__ float2 sb[2][NCHUNK];

    float2 a = g_lamT[p];
    float2 b = g_carry[j * PDIM + p];
    int cur = 0;
    sa[0][j] = a;
    sb[0][j] = b;
    __syncthreads();

#pragma unroll
    for (int s = 1; s < NCHUNK; s <<= 1) {
        float2 na = a, nb = b;
        if (j >= s) {
            const float2 pa = sa[cur][j - s];
            const float2 pb = sb[cur][j - s];
            na.x = a.x * pa.x - a.y * pa.y;
            na.y = a.x * pa.y + a.y * pa.x;
            nb.x = a.x * pb.x - a.y * pb.y + b.x;
            nb.y = a.x * pb.y + a.y * pb.x + b.y;
        }
        cur ^= 1;
        sa[cur][j] = na;
        sb[cur][j] = nb;
        a = na;
        b = nb;
        __syncthreads();
    }
    g_pfx[j * PDIM + p] = (j == 0) ? make_float2(0.0f, 0.0f) : sb[cur][j - 1];
}

// ---------------------------------------------------------------------------
extern "C" void kernel_launch(void* const* d_in, const int* in_sizes, int n_in,
                              void* d_out, int out_size) {
    const float* Lre     = (const float*)d_in[0];
    const float* Lim     = (const float*)d_in[1];
    const float* B       = (const float*)d_in[2];
    const float* C       = (const float*)d_in[3];
    const float* D       = (const float*)d_in[4];
    const float* logstep = (const float*)d_in[5];
    const float* u       = (const float*)d_in[6];
    float* y = (float*)d_out;

    cudaFuncSetAttribute(gemm_hmma_kernel<0>, cudaFuncAttributeMaxDynamicSharedMemorySize, SM_TOTAL);
    cudaFuncSetAttribute(gemm_hmma_kernel<1>, cudaFuncAttributeMaxDynamicSharedMemorySize, SM_TOTAL);

    prep_kernel<<<PDIM, HDIM>>>(Lre, Lim, B, C, logstep);

    dim3 grid(4, LSEQ / 64);
    gemm_hmma_kernel<0><<<grid, NTHREADS, SM_TOTAL>>>(u, nullptr, nullptr);
    carry_scan_par_kernel<<<PDIM, NCHUNK>>>();
    gemm_hmma_kernel<1><<<grid, NTHREADS, SM_TOTAL>>>(u, y, D);
}

// round 14
// speedup vs baseline: 1.1698x; 1.1698x over previous
#include <cuda_runtime.h>
#include <cuda_fp16.h>
#include <cstdint>

// Problem dims
#define LSEQ 32768
#define HDIM 256
#define PDIM 128
#define TCH  64                   // scan chunk length
#define NCHUNK (LSEQ / TCH)       // 512

// ---------------------------------------------------------------------------
__device__ __forceinline__ uint32_t smem_u32(const void* p) {
    uint32_t a;
    asm("{ .reg .u64 t; cvta.to.shared.u64 t, %1; cvt.u32.u64 %0, t; }" : "=r"(a) : "l"(p));
    return a;
}
__device__ __forceinline__ void ldsm_x4(uint32_t (&r)[4], uint32_t addr) {
    asm volatile("ldmatrix.sync.aligned.m8n8.x4.shared.b16 {%0,%1,%2,%3}, [%4];"
        : "=r"(r[0]), "=r"(r[1]), "=r"(r[2]), "=r"(r[3]) : "r"(addr));
}
__device__ __forceinline__ void mma_f16(float (&d)[4], const uint32_t (&a)[4],
                                        uint32_t b0, uint32_t b1) {
    asm volatile("mma.sync.aligned.m16n8k16.row.col.f32.f16.f16.f32 "
        "{%0,%1,%2,%3}, {%4,%5,%6,%7}, {%8,%9}, {%0,%1,%2,%3};"
        : "+f"(d[0]), "+f"(d[1]), "+f"(d[2]), "+f"(d[3])
        : "r"(a[0]), "r"(a[1]), "r"(a[2]), "r"(a[3]), "r"(b0), "r"(b1));
}
__device__ __forceinline__ void cp_async16(uint32_t dst, const void* src) {
    asm volatile("cp.async.cg.shared.global [%0], [%1], 16;" :: "r"(dst), "l"(src));
}
#define CP_COMMIT() asm volatile("cp.async.commit_group;")
#define CP_WAIT0()  asm volatile("cp.async.wait_group 0;")

// -------- device scratch (static) ------------------------------------------
__device__ __align__(128) __half g_W1h[256 * 256];  // GEMM1 B (fp16): [n=2p+ri][k=h]
__device__ __align__(128) __half g_W2h[256 * 256];  // GEMM2 B (fp16): [n=h][k=2p+ri]
__device__ float2 g_lam[PDIM];
__device__ float2 g_lamT[PDIM];
__device__ float2 g_lampow[TCH * PDIM];             // lambda^(t+1)
__device__ __align__(128) __half g_Bu16[LSEQ * 256];  // 16 MB: x_local in fp16
__device__ float2 g_carry[NCHUNK * PDIM];
__device__ float2 g_pfx[NCHUNK * PDIM];

// ---------------------------------------------------------------------------
// Prep
// ---------------------------------------------------------------------------
__global__ void prep_kernel(const float* __restrict__ Lre,
                            const float* __restrict__ Lim,
                            const float* __restrict__ B,
                            const float* __restrict__ C,
                            const float* __restrict__ logstep) {
    const int p = blockIdx.x;
    const int h = threadIdx.x;

    const float step = expf(logstep[p]);
    const float lr = Lre[p], li = Lim[p];
    const float ar = lr * step, ai = li * step;

    float s, c;
    const float mag = expf(ar);
    sincosf(ai, &s, &c);
    const float lam_re = mag * c, lam_im = mag * s;

    const float dr = lam_re - 1.0f, di = lam_im;
    const float inv_den = 1.0f / (lr * lr + li * li);
    const float fr = (dr * lr + di * li) * inv_den;
    const float fi = (di * lr - dr * li) * inv_den;

    const float b0 = B[(p * HDIM + h) * 2 + 0];
    const float b1 = B[(p * HDIM + h) * 2 + 1];
    g_W1h[(2 * p + 0) * 256 + h] = __float2half_rn(fr * b0 - fi * b1);
    g_W1h[(2 * p + 1) * 256 + h] = __float2half_rn(fr * b1 + fi * b0);

    g_W2h[h * 256 + 2 * p + 0] = __float2half_rn( 2.0f * C[(h * PDIM + p) * 2 + 0]);
    g_W2h[h * 256 + 2 * p + 1] = __float2half_rn(-2.0f * C[(h * PDIM + p) * 2 + 1]);

    if (h == 0) g_lam[p] = make_float2(lam_re, lam_im);

    if (h < TCH) {
        const float t = (float)(h + 1);
        float ss, cc;
        const float m = expf(ar * t);
        sincosf(ai * t, &ss, &cc);
        float2 pw = make_float2(m * cc, m * ss);
        g_lampow[h * PDIM + p] = pw;
        if (h == TCH - 1) g_lamT[p] = pw;
    }
}

// ---------------------------------------------------------------------------
// HMMA GEMM, M-tile 64, N-tile 128, BK=64, 8 warps (2x4), warp tile 32x32,
// 256 threads, 2 CTAs/SM. Plain fp16 operands.
// MODE 0: A=u (fp32->fp16), B=W1 -> Bu; epilogue: local scan, fp16 x_local+carry
// MODE 1: A=x_local (fp16 + fused prefix fix), B=W2 -> y (+ D*u)
// ---------------------------------------------------------------------------
#define NTHREADS 256
#define STAGE_SZ 24576               // A 8K | B 16K
#define OFF_A   0
#define OFF_B   8192
#define XS_STRIDE 132                // floats per row in epilogue staging
#define SM_TOTAL  (2 * STAGE_SZ)     // 49152

template <int MODE>
__global__ __launch_bounds__(NTHREADS, 2)
void gemm_hmma_kernel(const float* __restrict__ u,
                      float* __restrict__ y,
                      const float* __restrict__ Dv) {
    extern __shared__ char smem[];
    const uint32_t smem_base = smem_u32(smem);
    const int tid = threadIdx.x;
    const int wid = tid >> 5;
    const int lane = tid & 31;
    const int warp_m = wid >> 2;       // 0..1 (32 rows each)
    const int warp_n = wid & 3;        // 0..3 (32 cols each)
    const int n0 = blockIdx.x * 128;
    const int m0 = blockIdx.y * 64;

    const __half* Bhp = (MODE == 0) ? g_W1h : g_W2h;

    float acc[8][4];
#pragma unroll
    for (int i = 0; i < 8; i++)
#pragma unroll
        for (int j = 0; j < 4; j++) acc[i][j] = 0.0f;

    uint2 aReg2[4];   // MODE 0: packed fp16 from fp32 u
    uint4 aReg4[2];   // MODE 1: fp16 x_local + fixup

    auto loadA = [&](int c) {
        if (MODE == 0) {
#pragma unroll
            for (int j = 0; j < 4; j++) {
                const int i4 = tid + j * NTHREADS;   // 1024 float4s (64x64 fp32)
                const int row = i4 >> 4;
                const int fc = (i4 & 15) << 2;
                const float4 v = *reinterpret_cast<const float4*>(
                    u + (size_t)(m0 + row) * 256 + c * 64 + fc);
                uint2 hv;
                hv.x = ((uint32_t)__half_as_ushort(__float2half_rn(v.y)) << 16) |
                       __half_as_ushort(__float2half_rn(v.x));
                hv.y = ((uint32_t)__half_as_ushort(__float2half_rn(v.w)) << 16) |
                       __half_as_ushort(__float2half_rn(v.z));
                aReg2[j] = hv;
            }
        } else {
#pragma unroll
            for (int j = 0; j < 2; j++) {
                const int idx = tid + j * NTHREADS;  // 512 uint4s (64x64 fp16)
                const int row = idx >> 3;
                const int g8 = (idx & 7) << 3;
                const uint4 v = *reinterpret_cast<const uint4*>(
                    g_Bu16 + (size_t)(m0 + row) * 256 + c * 64 + g8);
                const __half2* hp = reinterpret_cast<const __half2*>(&v);
                const int l = m0 + row;
                const int pp = (c * 64 + g8) >> 1;
                const float2* pwp = g_lampow + (l & 63) * 128 + pp;
                const float2* cfp = g_pfx + (l >> 6) * 128 + pp;
                uint4 o;
                uint32_t* op = reinterpret_cast<uint32_t*>(&o);
#pragma unroll
                for (int q = 0; q < 4; q++) {
                    float2 f = __half22float2(hp[q]);
                    const float2 pw = pwp[q];
                    const float2 cf = cfp[q];
                    f.x += pw.x * cf.x - pw.y * cf.y;
                    f.y += pw.x * cf.y + pw.y * cf.x;
                    op[q] = (uint32_t)__half_as_ushort(__float2half_rn(f.y)) << 16 |
                            __half_as_ushort(__float2half_rn(f.x));
                }
                aReg4[j] = o;
            }
        }
    };
    auto storeA = [&](int buf) {
        if (MODE == 0) {
#pragma unroll
            for (int j = 0; j < 4; j++) {
                const int i4 = tid + j * NTHREADS;
                const int row = i4 >> 4;
                const int fc = (i4 & 15) << 2;
                const uint32_t off = (uint32_t)(buf * STAGE_SZ + row * 128 +
                                     (((fc >> 3) ^ (row & 7)) << 4) + ((fc & 4) << 1));
                *reinterpret_cast<uint2*>(smem + OFF_A + off) = aReg2[j];
            }
        } else {
#pragma unroll
            for (int j = 0; j < 2; j++) {
                const int idx = tid + j * NTHREADS;
                const int row = idx >> 3;
                const int un = idx & 7;
                const uint32_t off = (uint32_t)(buf * STAGE_SZ + row * 128 +
                                     ((un ^ (row & 7)) << 4));
                *reinterpret_cast<uint4*>(smem + OFF_A + off) = aReg4[j];
            }
        }
    };
    auto issueB = [&](int c, int buf) {
#pragma unroll
        for (int j = 0; j < 4; j++) {
            const int i = tid + j * NTHREADS;      // 1024 16B units (128x64 fp16)
            const int row = i >> 3;
            const int un = i & 7;
            const uint32_t off = (uint32_t)(buf * STAGE_SZ + row * 128 +
                                 ((un ^ (row & 7)) << 4));
            cp_async16(smem_base + OFF_B + off,
                       Bhp + (size_t)(n0 + row) * 256 + c * 64 + un * 8);
        }
        CP_COMMIT();
    };
    auto compute = [&](int buf) {
        const uint32_t ab = smem_base + OFF_A + buf * STAGE_SZ;
        const uint32_t bb = smem_base + OFF_B + buf * STAGE_SZ;
        const int arow = (lane & 7) + ((lane >> 3) & 1) * 8;
        const int akc = lane >> 4;
        uint32_t baseA[2], baseB[2];
#pragma unroll
        for (int mi = 0; mi < 2; mi++) {
            const int row = warp_m * 32 + mi * 16 + arow;
            baseA[mi] = (uint32_t)(row * 128 + ((row & 7) << 4));
        }
#pragma unroll
        for (int hg = 0; hg < 2; hg++) {
            const int row = warp_n * 32 + hg * 16 + arow;
            baseB[hg] = (uint32_t)(row * 128 + ((row & 7) << 4));
        }
#pragma unroll
        for (int kk = 0; kk < 4; kk++) {
            const uint32_t kcx = (uint32_t)((kk * 2 + akc) << 4);
            uint32_t af[2][4], bq[2][4];
#pragma unroll
            for (int mi = 0; mi < 2; mi++)
                ldsm_x4(af[mi], ab + (baseA[mi] ^ kcx));
#pragma unroll
            for (int hg = 0; hg < 2; hg++)
                ldsm_x4(bq[hg], bb + (baseB[hg] ^ kcx));
#pragma unroll
            for (int mi = 0; mi < 2; mi++)
#pragma unroll
                for (int ni = 0; ni < 4; ni++) {
                    const int hg = ni >> 1, s2 = ni & 1;
                    mma_f16(acc[mi * 4 + ni], af[mi], bq[hg][s2], bq[hg][s2 + 2]);
                }
        }
    };

    // ---- pipelined mainloop over 4 K-chunks ----
    issueB(0, 0);
    loadA(0);
    for (int c = 0; c < 4; c++) {
        const int buf = c & 1;
        storeA(buf);
        CP_WAIT0();
        __syncthreads();
        if (c < 3) {
            issueB(c + 1, buf ^ 1);
            loadA(c + 1);
        }
        compute(buf);
    }
    __syncthreads();   // before SMEM reuse

    if (MODE == 0) {
        // ---- epilogue: stage Bu tile in SMEM, local scan, write fp16 x_local ----
        float* xs = reinterpret_cast<float*>(smem);
#pragma unroll
        for (int mi = 0; mi < 2; mi++) {
            const int r0 = warp_m * 32 + mi * 16 + (lane >> 2);
#pragma unroll
            for (int ni = 0; ni < 4; ni++) {
                const int cc = warp_n * 32 + ni * 8 + (lane & 3) * 2;
                const float* a = acc[mi * 4 + ni];
                *reinterpret_cast<float2*>(xs + r0 * XS_STRIDE + cc) = make_float2(a[0], a[1]);
                *reinterpret_cast<float2*>(xs + (r0 + 8) * XS_STRIDE + cc) = make_float2(a[2], a[3]);
            }
        }
        __syncthreads();

        if (tid < 64) {
            const int pg = (n0 >> 1) + tid;          // this CTA covers 64 states
            const float2 lam = g_lam[pg];
            float2 x = make_float2(0.0f, 0.0f);
            float* base = xs + 2 * tid;
#pragma unroll 4
            for (int t = 0; t < 64; t++) {
                float2 b = *reinterpret_cast<float2*>(base + t * XS_STRIDE);
                const float nr = lam.x * x.x - lam.y * x.y + b.x;
                const float ni2 = lam.x * x.y + lam.y * x.x + b.y;
                x.x = nr; x.y = ni2;
                *reinterpret_cast<float2*>(base + t * XS_STRIDE) = x;
            }
            g_carry[(m0 >> 6) * 128 + pg] = x;       // one chunk per CTA (BM=64=TCH)
        }
        __syncthreads();

#pragma unroll
        for (int j = 0; j < 4; j++) {
            const int idx = tid + j * NTHREADS;      // 1024 uint4s (64x128 fp16)
            const int row = idx >> 4;
            const int g8 = (idx & 15) << 3;
            const float* src = xs + row * XS_STRIDE + g8;
            uint4 o;
            uint32_t* op = reinterpret_cast<uint32_t*>(&o);
#pragma unroll
            for (int q = 0; q < 4; q++) {
                const float2 f = *reinterpret_cast<const float2*>(src + 2 * q);
                op[q] = (uint32_t)__half_as_ushort(__float2half_rn(f.y)) << 16 |
                        __half_as_ushort(__float2half_rn(f.x));
            }
            *reinterpret_cast<uint4*>(g_Bu16 + (size_t)(m0 + row) * 256 + n0 + g8) = o;
        }
    } else {
        // ---- epilogue: y = acc + D*u, direct ----
#pragma unroll
        for (int mi = 0; mi < 2; mi++) {
            const int r0 = m0 + warp_m * 32 + mi * 16 + (lane >> 2);
#pragma unroll
            for (int ni = 0; ni < 4; ni++) {
                const int gc = n0 + warp_n * 32 + ni * 8 + (lane & 3) * 2;
                const float d0 = __ldg(Dv + gc), d1 = __ldg(Dv + gc + 1);
                const float* a = acc[mi * 4 + ni];
                const float2 u0 = *reinterpret_cast<const float2*>(u + (size_t)r0 * 256 + gc);
                const float2 u1 = *reinterpret_cast<const float2*>(u + (size_t)(r0 + 8) * 256 + gc);
                *reinterpret_cast<float2*>(y + (size_t)r0 * 256 + gc) =
                    make_float2(a[0] + d0 * u0.x, a[1] + d1 * u0.y);
                *reinterpret_cast<float2*>(y + (size_t)(r0 + 8) * 256 + gc) =
                    make_float2(a[2] + d0 * u1.x, a[3] + d1 * u1.y);
            }
        }
    }
}

// ---------------------------------------------------------------------------
// Parallel carry scan across chunks (Kogge-Stone), exclusive prefix -> g_pfx.
// ---------------------------------------------------------------------------
__global__ __launch_bounds__(NCHUNK)
void carry_scan_par_kernel() {
    const int p = blockIdx.x;
    const int j = threadIdx.x;
    __shared__ float2 sa[2][NCHUNK];
    __shared__ float2 sb[2][NCHUNK];

    float2 a = g_lamT[p];
    float2 b = g_carry[j * PDIM + p];
    int cur = 0;
    sa[0][j] = a;
    sb[0][j] = b;
    __syncthreads();

#pragma unroll
    for (int s = 1; s < NCHUNK; s <<= 1) {
        float2 na = a, nb = b;
        if (j >= s) {
            const float2 pa = sa[cur][j - s];
            const float2 pb = sb[cur][j - s];
            na.x = a.x * pa.x - a.y * pa.y;
            na.y = a.x * pa.y + a.y * pa.x;
            nb.x = a.x * pb.x - a.y * pb.y + b.x;
            nb.y = a.x * pb.y + a.y * pb.x + b.y;
        }
        cur ^= 1;
        sa[cur][j] = na;
        sb[cur][j] = nb;
        a = na;
        b = nb;
        __syncthreads();
    }
    g_pfx[j * PDIM + p] = (j == 0) ? make_float2(0.0f, 0.0f) : sb[cur][j - 1];
}

// ---------------------------------------------------------------------------
extern "C" void kernel_launch(void* const* d_in, const int* in_sizes, int n_in,
                              void* d_out, int out_size) {
    const float* Lre     = (const float*)d_in[0];
    const float* Lim     = (const float*)d_in[1];
    const float* B       = (const float*)d_in[2];
    const float* C       = (const float*)d_in[3];
    const float* D       = (const float*)d_in[4];
    const float* logstep = (const float*)d_in[5];
    const float* u       = (const float*)d_in[6];
    float* y = (float*)d_out;

    cudaFuncSetAttribute(gemm_hmma_kernel<0>, cudaFuncAttributeMaxDynamicSharedMemorySize, SM_TOTAL);
    cudaFuncSetAttribute(gemm_hmma_kernel<1>, cudaFuncAttributeMaxDynamicSharedMemorySize, SM_TOTAL);

    prep_kernel<<<PDIM, HDIM>>>(Lre, Lim, B, C, logstep);

    dim3 grid(2, LSEQ / 64);
    gemm_hmma_kernel<0><<<grid, NTHREADS, SM_TOTAL>>>(u, nullptr, nullptr);
    carry_scan_par_kernel<<<PDIM, NCHUNK>>>();
    gemm_hmma_kernel<1><<<grid, NTHREADS, SM_TOTAL>>>(u, y, D);
}

// round 15
// speedup vs baseline: 1.2001x; 1.0259x over previous
#include <cuda_runtime.h>
#include <cuda_fp16.h>
#include <cstdint>

// Problem dims
#define LSEQ 32768
#define HDIM 256
#define PDIM 128
#define TCH  64                   // scan chunk length
#define NCHUNK (LSEQ / TCH)       // 512

// ---------------------------------------------------------------------------
__device__ __forceinline__ uint32_t smem_u32(const void* p) {
    uint32_t a;
    asm("{ .reg .u64 t; cvta.to.shared.u64 t, %1; cvt.u32.u64 %0, t; }" : "=r"(a) : "l"(p));
    return a;
}
__device__ __forceinline__ void ldsm_x4(uint32_t (&r)[4], uint32_t addr) {
    asm volatile("ldmatrix.sync.aligned.m8n8.x4.shared.b16 {%0,%1,%2,%3}, [%4];"
        : "=r"(r[0]), "=r"(r[1]), "=r"(r[2]), "=r"(r[3]) : "r"(addr));
}
__device__ __forceinline__ void mma_f16(float (&d)[4], const uint32_t (&a)[4],
                                        uint32_t b0, uint32_t b1) {
    asm volatile("mma.sync.aligned.m16n8k16.row.col.f32.f16.f16.f32 "
        "{%0,%1,%2,%3}, {%4,%5,%6,%7}, {%8,%9}, {%0,%1,%2,%3};"
        : "+f"(d[0]), "+f"(d[1]), "+f"(d[2]), "+f"(d[3])
        : "r"(a[0]), "r"(a[1]), "r"(a[2]), "r"(a[3]), "r"(b0), "r"(b1));
}
__device__ __forceinline__ void cp_async16(uint32_t dst, const void* src) {
    asm volatile("cp.async.cg.shared.global [%0], [%1], 16;" :: "r"(dst), "l"(src));
}
#define CP_COMMIT() asm volatile("cp.async.commit_group;")
#define CP_WAIT0()  asm volatile("cp.async.wait_group 0;")

// -------- device scratch (static) ------------------------------------------
__device__ __align__(128) __half g_W1h[256 * 256];  // GEMM1 B (fp16): [n=2p+ri][k=h]
__device__ __align__(128) __half g_W2h[256 * 256];  // GEMM2 B (fp16): [n=h][k=2p+ri]
__device__ float2 g_lam[PDIM];
__device__ float2 g_lamT[PDIM];
__device__ float2 g_lampow[TCH * PDIM];             // lambda^(t+1)
__device__ __align__(128) __half g_Bu16[LSEQ * 256];  // 16 MB: x_local in fp16
__device__ float2 g_carry[NCHUNK * PDIM];
__device__ float2 g_pfx[NCHUNK * PDIM];

// ---------------------------------------------------------------------------
// Prep
// ---------------------------------------------------------------------------
__global__ void prep_kernel(const float* __restrict__ Lre,
                            const float* __restrict__ Lim,
                            const float* __restrict__ B,
                            const float* __restrict__ C,
                            const float* __restrict__ logstep) {
    const int p = blockIdx.x;
    const int h = threadIdx.x;

    const float step = expf(logstep[p]);
    const float lr = Lre[p], li = Lim[p];
    const float ar = lr * step, ai = li * step;

    float s, c;
    const float mag = expf(ar);
    sincosf(ai, &s, &c);
    const float lam_re = mag * c, lam_im = mag * s;

    const float dr = lam_re - 1.0f, di = lam_im;
    const float inv_den = 1.0f / (lr * lr + li * li);
    const float fr = (dr * lr + di * li) * inv_den;
    const float fi = (di * lr - dr * li) * inv_den;

    const float b0 = B[(p * HDIM + h) * 2 + 0];
    const float b1 = B[(p * HDIM + h) * 2 + 1];
    g_W1h[(2 * p + 0) * 256 + h] = __float2half_rn(fr * b0 - fi * b1);
    g_W1h[(2 * p + 1) * 256 + h] = __float2half_rn(fr * b1 + fi * b0);

    g_W2h[h * 256 + 2 * p + 0] = __float2half_rn( 2.0f * C[(h * PDIM + p) * 2 + 0]);
    g_W2h[h * 256 + 2 * p + 1] = __float2half_rn(-2.0f * C[(h * PDIM + p) * 2 + 1]);

    if (h == 0) g_lam[p] = make_float2(lam_re, lam_im);

    if (h < TCH) {
        const float t = (float)(h + 1);
        float ss, cc;
        const float m = expf(ar * t);
        sincosf(ai * t, &ss, &cc);
        float2 pw = make_float2(m * cc, m * ss);
        g_lampow[h * PDIM + p] = pw;
        if (h == TCH - 1) g_lamT[p] = pw;
    }
}

// ---------------------------------------------------------------------------
// HMMA GEMM, CTA tile 64x128, BK=64, 4 warps (2Mx2N), warp tile 32x64,
// 128 threads, 4 CTAs/SM. Plain fp16 operands.
// MODE 0: A=u (fp32->fp16), B=W1 -> Bu; epilogue: local scan, fp16 x_local+carry
// MODE 1: A=x_local (fp16 + fused prefix fix), B=W2 -> y (+ D*u)
// ---------------------------------------------------------------------------
#define NTHREADS 128
#define STAGE_SZ 24576               // A 8K | B 16K
#define OFF_A   0
#define OFF_B   8192
#define XS_STRIDE 132                // floats per row in epilogue staging
#define SM_TOTAL  (2 * STAGE_SZ)     // 49152

template <int MODE>
__global__ __launch_bounds__(NTHREADS, 4)
void gemm_hmma_kernel(const float* __restrict__ u,
                      float* __restrict__ y,
                      const float* __restrict__ Dv) {
    extern __shared__ char smem[];
    const uint32_t smem_base = smem_u32(smem);
    const int tid = threadIdx.x;
    const int wid = tid >> 5;
    const int lane = tid & 31;
    const int warp_m = wid >> 1;       // 0..1 (32 rows each)
    const int warp_n = wid & 1;        // 0..1 (64 cols each)
    const int n0 = blockIdx.x * 128;
    const int m0 = blockIdx.y * 64;

    const __half* Bhp = (MODE == 0) ? g_W1h : g_W2h;

    float acc[16][4];
#pragma unroll
    for (int i = 0; i < 16; i++)
#pragma unroll
        for (int j = 0; j < 4; j++) acc[i][j] = 0.0f;

    uint2 aReg2[8];   // MODE 0: packed fp16 from fp32 u
    uint4 aReg4[4];   // MODE 1: fp16 x_local + fixup

    auto loadA = [&](int c) {
        if (MODE == 0) {
#pragma unroll
            for (int j = 0; j < 8; j++) {
                const int i4 = tid + j * NTHREADS;   // 1024 float4s (64x64 fp32)
                const int row = i4 >> 4;
                const int fc = (i4 & 15) << 2;
                const float4 v = *reinterpret_cast<const float4*>(
                    u + (size_t)(m0 + row) * 256 + c * 64 + fc);
                uint2 hv;
                hv.x = ((uint32_t)__half_as_ushort(__float2half_rn(v.y)) << 16) |
                       __half_as_ushort(__float2half_rn(v.x));
                hv.y = ((uint32_t)__half_as_ushort(__float2half_rn(v.w)) << 16) |
                       __half_as_ushort(__float2half_rn(v.z));
                aReg2[j] = hv;
            }
        } else {
#pragma unroll
            for (int j = 0; j < 4; j++) {
                const int idx = tid + j * NTHREADS;  // 512 uint4s (64x64 fp16)
                const int row = idx >> 3;
                const int g8 = (idx & 7) << 3;
                const uint4 v = *reinterpret_cast<const uint4*>(
                    g_Bu16 + (size_t)(m0 + row) * 256 + c * 64 + g8);
                const __half2* hp = reinterpret_cast<const __half2*>(&v);
                const int l = m0 + row;
                const int pp = (c * 64 + g8) >> 1;
                const float2* pwp = g_lampow + (l & 63) * 128 + pp;
                const float2* cfp = g_pfx + (l >> 6) * 128 + pp;
                uint4 o;
                uint32_t* op = reinterpret_cast<uint32_t*>(&o);
#pragma unroll
                for (int q = 0; q < 4; q++) {
                    float2 f = __half22float2(hp[q]);
                    const float2 pw = pwp[q];
                    const float2 cf = cfp[q];
                    f.x += pw.x * cf.x - pw.y * cf.y;
                    f.y += pw.x * cf.y + pw.y * cf.x;
                    op[q] = (uint32_t)__half_as_ushort(__float2half_rn(f.y)) << 16 |
                            __half_as_ushort(__float2half_rn(f.x));
                }
                aReg4[j] = o;
            }
        }
    };
    auto storeA = [&](int buf) {
        if (MODE == 0) {
#pragma unroll
            for (int j = 0; j < 8; j++) {
                const int i4 = tid + j * NTHREADS;
                const int row = i4 >> 4;
                const int fc = (i4 & 15) << 2;
                const uint32_t off = (uint32_t)(buf * STAGE_SZ + row * 128 +
                                     (((fc >> 3) ^ (row & 7)) << 4) + ((fc & 4) << 1));
                *reinterpret_cast<uint2*>(smem + OFF_A + off) = aReg2[j];
            }
        } else {
#pragma unroll
            for (int j = 0; j < 4; j++) {
                const int idx = tid + j * NTHREADS;
                const int row = idx >> 3;
                const int un = idx & 7;
                const uint32_t off = (uint32_t)(buf * STAGE_SZ + row * 128 +
                                     ((un ^ (row & 7)) << 4));
                *reinterpret_cast<uint4*>(smem + OFF_A + off) = aReg4[j];
            }
        }
    };
    auto issueB = [&](int c, int buf) {
#pragma unroll
        for (int j = 0; j < 8; j++) {
            const int i = tid + j * NTHREADS;      // 1024 16B units (128x64 fp16)
            const int row = i >> 3;
            const int un = i & 7;
            const uint32_t off = (uint32_t)(buf * STAGE_SZ + row * 128 +
                                 ((un ^ (row & 7)) << 4));
            cp_async16(smem_base + OFF_B + off,
                       Bhp + (size_t)(n0 + row) * 256 + c * 64 + un * 8);
        }
        CP_COMMIT();
    };
    auto compute = [&](int buf) {
        const uint32_t ab = smem_base + OFF_A + buf * STAGE_SZ;
        const uint32_t bb = smem_base + OFF_B + buf * STAGE_SZ;
        const int arow = (lane & 7) + ((lane >> 3) & 1) * 8;
        const int akc = lane >> 4;
        uint32_t baseA[2], baseB[4];
#pragma unroll
        for (int mi = 0; mi < 2; mi++) {
            const int row = warp_m * 32 + mi * 16 + arow;
            baseA[mi] = (uint32_t)(row * 128 + ((row & 7) << 4));
        }
#pragma unroll
        for (int hg = 0; hg < 4; hg++) {
            const int row = warp_n * 64 + hg * 16 + arow;
            baseB[hg] = (uint32_t)(row * 128 + ((row & 7) << 4));
        }
#pragma unroll
        for (int kk = 0; kk < 4; kk++) {
            const uint32_t kcx = (uint32_t)((kk * 2 + akc) << 4);
            uint32_t af[2][4], bq[4][4];
#pragma unroll
            for (int mi = 0; mi < 2; mi++)
                ldsm_x4(af[mi], ab + (baseA[mi] ^ kcx));
#pragma unroll
            for (int hg = 0; hg < 4; hg++)
                ldsm_x4(bq[hg], bb + (baseB[hg] ^ kcx));
#pragma unroll
            for (int mi = 0; mi < 2; mi++)
#pragma unroll
                for (int ni = 0; ni < 8; ni++) {
                    const int hg = ni >> 1, s2 = ni & 1;
                    mma_f16(acc[mi * 8 + ni], af[mi], bq[hg][s2], bq[hg][s2 + 2]);
                }
        }
    };

    // ---- pipelined mainloop over 4 K-chunks ----
    issueB(0, 0);
    loadA(0);
    for (int c = 0; c < 4; c++) {
        const int buf = c & 1;
        storeA(buf);
        CP_WAIT0();
        __syncthreads();
        if (c < 3) {
            issueB(c + 1, buf ^ 1);
            loadA(c + 1);
        }
        compute(buf);
    }
    __syncthreads();   // before SMEM reuse

    if (MODE == 0) {
        // ---- epilogue: stage Bu tile in SMEM, local scan, write fp16 x_local ----
        float* xs = reinterpret_cast<float*>(smem);
#pragma unroll
        for (int mi = 0; mi < 2; mi++) {
            const int r0 = warp_m * 32 + mi * 16 + (lane >> 2);
#pragma unroll
            for (int ni = 0; ni < 8; ni++) {
                const int cc = warp_n * 64 + ni * 8 + (lane & 3) * 2;
                const float* a = acc[mi * 8 + ni];
                *reinterpret_cast<float2*>(xs + r0 * XS_STRIDE + cc) = make_float2(a[0], a[1]);
                *reinterpret_cast<float2*>(xs + (r0 + 8) * XS_STRIDE + cc) = make_float2(a[2], a[3]);
            }
        }
        __syncthreads();

        if (tid < 64) {
            const int pg = (n0 >> 1) + tid;          // this CTA covers 64 states
            const float2 lam = g_lam[pg];
            float2 x = make_float2(0.0f, 0.0f);
            float* base = xs + 2 * tid;
#pragma unroll 4
            for (int t = 0; t < 64; t++) {
                float2 b = *reinterpret_cast<float2*>(base + t * XS_STRIDE);
                const float nr = lam.x * x.x - lam.y * x.y + b.x;
                const float ni2 = lam.x * x.y + lam.y * x.x + b.y;
                x.x = nr; x.y = ni2;
                *reinterpret_cast<float2*>(base + t * XS_STRIDE) = x;
            }
            g_carry[(m0 >> 6) * 128 + pg] = x;       // one chunk per CTA (BM=64=TCH)
        }
        __syncthreads();

#pragma unroll
        for (int j = 0; j < 8; j++) {
            const int idx = tid + j * NTHREADS;      // 1024 uint4s (64x128 fp16)
            const int row = idx >> 4;
            const int g8 = (idx & 15) << 3;
            const float* src = xs + row * XS_STRIDE + g8;
            uint4 o;
            uint32_t* op = reinterpret_cast<uint32_t*>(&o);
#pragma unroll
            for (int q = 0; q < 4; q++) {
                const float2 f = *reinterpret_cast<const float2*>(src + 2 * q);
                op[q] = (uint32_t)__half_as_ushort(__float2half_rn(f.y)) << 16 |
                        __half_as_ushort(__float2half_rn(f.x));
            }
            *reinterpret_cast<uint4*>(g_Bu16 + (size_t)(m0 + row) * 256 + n0 + g8) = o;
        }
    } else {
        // ---- epilogue: y = acc + D*u, direct ----
#pragma unroll
        for (int mi = 0; mi < 2; mi++) {
            const int r0 = m0 + warp_m * 32 + mi * 16 + (lane >> 2);
#pragma unroll
            for (int ni = 0; ni < 8; ni++) {
                const int gc = n0 + warp_n * 64 + ni * 8 + (lane & 3) * 2;
                const float d0 = __ldg(Dv + gc), d1 = __ldg(Dv + gc + 1);
                const float* a = acc[mi * 8 + ni];
                const float2 u0 = *reinterpret_cast<const float2*>(u + (size_t)r0 * 256 + gc);
                const float2 u1 = *reinterpret_cast<const float2*>(u + (size_t)(r0 + 8) * 256 + gc);
                *reinterpret_cast<float2*>(y + (size_t)r0 * 256 + gc) =
                    make_float2(a[0] + d0 * u0.x, a[1] + d1 * u0.y);
                *reinterpret_cast<float2*>(y + (size_t)(r0 + 8) * 256 + gc) =
                    make_float2(a[2] + d0 * u1.x, a[3] + d1 * u1.y);
            }
        }
    }
}

// ---------------------------------------------------------------------------
// Parallel carry scan across chunks (Kogge-Stone), exclusive prefix -> g_pfx.
// ---------------------------------------------------------------------------
__global__ __launch_bounds__(NCHUNK)
void carry_scan_par_kernel() {
    const int p = blockIdx.x;
    const int j = threadIdx.x;
    __shared__ float2 sa[2][NCHUNK];
    __shared__ float2 sb[2][NCHUNK];

    float2 a = g_lamT[p];
    float2 b = g_carry[j * PDIM + p];
    int cur = 0;
    sa[0][j] = a;
    sb[0][j] = b;
    __syncthreads();

#pragma unroll
    for (int s = 1; s < NCHUNK; s <<= 1) {
        float2 na = a, nb = b;
        if (j >= s) {
            const float2 pa = sa[cur][j - s];
            const float2 pb = sb[cur][j - s];
            na.x = a.x * pa.x - a.y * pa.y;
            na.y = a.x * pa.y + a.y * pa.x;
            nb.x = a.x * pb.x - a.y * pb.y + b.x;
            nb.y = a.x * pb.y + a.y * pb.x + b.y;
        }
        cur ^= 1;
        sa[cur][j] = na;
        sb[cur][j] = nb;
        a = na;
        b = nb;
        __syncthreads();
    }
    g_pfx[j * PDIM + p] = (j == 0) ? make_float2(0.0f, 0.0f) : sb[cur][j - 1];
}

// ---------------------------------------------------------------------------
extern "C" void kernel_launch(void* const* d_in, const int* in_sizes, int n_in,
                              void* d_out, int out_size) {
    const float* Lre     = (const float*)d_in[0];
    const float* Lim     = (const float*)d_in[1];
    const float* B       = (const float*)d_in[2];
    const float* C       = (const float*)d_in[3];
    const float* D       = (const float*)d_in[4];
    const float* logstep = (const float*)d_in[5];
    const float* u       = (const float*)d_in[6];
    float* y = (float*)d_out;

    cudaFuncSetAttribute(gemm_hmma_kernel<0>, cudaFuncAttributeMaxDynamicSharedMemorySize, SM_TOTAL);
    cudaFuncSetAttribute(gemm_hmma_kernel<1>, cudaFuncAttributeMaxDynamicSharedMemorySize, SM_TOTAL);

    prep_kernel<<<PDIM, HDIM>>>(Lre, Lim, B, C, logstep);

    dim3 grid(2, LSEQ / 64);
    gemm_hmma_kernel<0><<<grid, NTHREADS, SM_TOTAL>>>(u, nullptr, nullptr);
    carry_scan_par_kernel<<<PDIM, NCHUNK>>>();
    gemm_hmma_kernel<1><<<grid, NTHREADS, SM_TOTAL>>>(u, y, D);
}